// round 8
// baseline (speedup 1.0000x reference)
#include <cuda_runtime.h>
#include <cuda_bf16.h>
#include <cuda_fp16.h>
#include <cuda_fp8.h>
#include <cstdint>

#define VOCAB 10000
#define EMBD 100
#define EMBP 128
#define SEQ 80
#define UNITS 512
#define BATCH 2048
#define BT (BATCH*SEQ)
#define MAXS (SEQ+3)        // 83 wavefront steps

#define HSCALE 256.0f
#define WSCALE 64.0f
#define DESCALE (1.0f/(HSCALE*WSCALE))

#define RGRIDX 8
#define RGRIDY 16
#define NCTA (RGRIDX*RGRIDY)   // 128

// SMEM layout (XOR-swizzled, no pads)
#define SB_U 0                  // 4 x [64n][512k] fp8 = 131072
#define SB_A 131072             // 3 x [128m][128k] = 49152
#define SB_W 180224             // 3 x [64n][128k]  = 24576
#define SM_TOTAL 204800

// ---------------- device scratch ----------------
__device__ __align__(16) uint8_t g_X0[(size_t)BT * EMBP];        // fp8 * HSCALE
__device__ __align__(16) uint8_t g_H[4][(size_t)BT * UNITS];     // fp8 * HSCALE, t-major
__device__ __align__(16) uint8_t g_W0t[512 * 128];               // W1^T [n][k] fp8*WSCALE
__device__ __align__(16) uint8_t g_Wt[3][512 * 512];             // W2..4^T
__device__ __align__(16) uint8_t g_Ut[4][512 * 512];             // U1..4^T
__device__ unsigned g_bar2[RGRIDY][96];

// ---------------- PTX helpers ----------------
__device__ __forceinline__ uint32_t smaddr(const void* p) {
    return (uint32_t)__cvta_generic_to_shared(p);
}
__device__ __forceinline__ void cpa16(uint32_t dst, const void* src) {
    asm volatile("cp.async.cg.shared.global [%0], [%1], 16;\n" :: "r"(dst), "l"(src));
}
__device__ __forceinline__ void cp_commit() { asm volatile("cp.async.commit_group;\n"); }
template<int N> __device__ __forceinline__ void cp_wait() {
    asm volatile("cp.async.wait_group %0;\n" :: "n"(N));
}
__device__ __forceinline__ void ldsm4(uint32_t (&r)[4], uint32_t addr) {
    asm volatile("ldmatrix.sync.aligned.m8n8.x4.shared.b16 {%0,%1,%2,%3}, [%4];\n"
                 : "=r"(r[0]), "=r"(r[1]), "=r"(r[2]), "=r"(r[3]) : "r"(addr));
}
__device__ __forceinline__ void mma_fp8(float (&d)[4], const uint32_t (&a)[4],
                                        uint32_t b0, uint32_t b1) {
    asm volatile("mma.sync.aligned.m16n8k32.row.col.f32.e4m3.e4m3.f32 "
                 "{%0,%1,%2,%3}, {%4,%5,%6,%7}, {%8,%9}, {%0,%1,%2,%3};\n"
                 : "+f"(d[0]), "+f"(d[1]), "+f"(d[2]), "+f"(d[3])
                 : "r"(a[0]), "r"(a[1]), "r"(a[2]), "r"(a[3]), "r"(b0), "r"(b1));
}
__device__ __forceinline__ uint8_t to_fp8(float v) {
    return (uint8_t)__nv_cvt_float_to_fp8(v, __NV_SATFINITE, __NV_E4M3);
}
// xor-swizzle: byte col cb (mult of 16) within row r
#define SWZ(cb, r) ((cb) ^ (((r) & 7u) << 4))

// ---------------- prep kernels ----------------
__global__ void cvtW_kernel(const float* __restrict__ W1, const float* __restrict__ W2,
                            const float* __restrict__ W3, const float* __restrict__ W4) {
    int i = blockIdx.x * blockDim.x + threadIdx.x;
    if (i < 512 * 128) {                       // W1 -> g_W0t [512n][128k]
        int n = i >> 7, k = i & 127;
        g_W0t[i] = to_fp8(k < EMBD ? W1[(size_t)k * 512 + n] * WSCALE : 0.0f);
        return;
    }
    i -= 512 * 128;
    if (i >= 3 * 512 * 512) return;
    int m = i / (512 * 512), r = i - m * 512 * 512;
    int n = r >> 9, k = r & 511;
    const float* Wm = (m == 0) ? W2 : (m == 1) ? W3 : W4;
    g_Wt[m][r] = to_fp8(Wm[(size_t)k * 512 + n] * WSCALE);
}

__global__ void cvtU_kernel(const float* __restrict__ U1, const float* __restrict__ U2,
                            const float* __restrict__ U3, const float* __restrict__ U4) {
    int i = blockIdx.x * blockDim.x + threadIdx.x;
    if (i >= 4 * 512 * 512) return;
    int m = i >> 18, r = i & (512 * 512 - 1);
    int n = r >> 9, k = r & 511;
    const float* Um = (m == 0) ? U1 : (m == 1) ? U2 : (m == 2) ? U3 : U4;
    g_Ut[m][r] = to_fp8(Um[(size_t)k * 512 + n] * WSCALE);
}

__global__ void embed_kernel(const int* __restrict__ tokens, const float* __restrict__ emb) {
    int i = blockIdx.x * blockDim.x + threadIdx.x;
    if (i >= BT * EMBP) return;
    int r = i >> 7, k = i & 127;
    int t = r / BATCH, b = r - t * BATCH;
    float v = (k < EMBD) ? emb[(size_t)tokens[b * SEQ + t] * EMBD + k] * HSCALE : 0.0f;
    g_X0[i] = to_fp8(v);
}

__global__ void zero0_kernel() {
    int i = threadIdx.x;
    for (; i < RGRIDY * 96 / 2; i += blockDim.x) ((unsigned*)g_bar2)[i] = 0u;
}
__global__ void zero1_kernel() {
    int i = threadIdx.x;
    for (; i < RGRIDY * 96 / 2; i += blockDim.x)
        ((unsigned*)g_bar2)[RGRIDY * 96 / 2 + i] = 0u;
}

// ================= wavefront kernel: all 4 layers, 83 global steps =================
// CTA c: n-cols [64*(c&7)..), batch rows [128*(c>>3)..). Per step, for each active layer l
// (t = s-l): acc = h_{l-1}(t)@W_l + h_l(t-1)@U_l (both fp8 mma into one fp32 acc),
// h_l(t) = tanh(acc*DESCALE + b_l). U resident in SMEM; W + activations streamed (3-buf ring).
__global__ __launch_bounds__(256, 1) void wave_kernel(
    const float* __restrict__ b0p, const float* __restrict__ b1p,
    const float* __restrict__ b2p, const float* __restrict__ b3p)
{
    extern __shared__ __align__(128) uint8_t smbuf[];
    const uint32_t sb = smaddr(smbuf);

    const int tid = threadIdx.x, lane = tid & 31, wid = tid >> 5;
    const int wm = wid & 3, wn = wid >> 2;
    const int colBase = (blockIdx.x & 7) * 64;
    const int rowBase = (blockIdx.x >> 3) * 128;
    const int ygrp = blockIdx.x >> 3;

    const float* bias[4] = {b0p, b1p, b2p, b3p};

    // ---- load resident U slices: 4 x [64n][512k], swizzled ----
    #pragma unroll
    for (int i = 0; i < 32; i++) {
        int u = tid + i * 256;                 // 0..8191 granules
        int l = u >> 11;                       // 2048 granules per layer
        int v = u & 2047;
        int row = v >> 5, g = (v & 31) << 4;
        cpa16(sb + SB_U + l * 32768 + row * 512 + SWZ(g, row),
              g_Ut[l] + (size_t)(colBase + row) * 512 + g);
    }
    cp_commit();
    cp_wait<0>();
    __syncthreads();

    const int r0 = rowBase + wm * 32 + (lane >> 2);
    const int c0l = wn * 32 + (lane & 3) * 2;          // local col within 64
    float acc[2][4][4];
    #pragma unroll
    for (int mt = 0; mt < 2; mt++)
        #pragma unroll
        for (int nf = 0; nf < 4; nf++)
            #pragma unroll
            for (int j = 0; j < 4; j++) acc[mt][nf][j] = 0.0f;

    for (int s = 0; s < MAXS; ++s) {
        // active jobs this step
        int jl[4], jt[4], jnw[4], jnp[4], nj = 0, tot = 0;
        #pragma unroll
        for (int l = 0; l < 4; l++) {
            int t = s - l;
            if (t >= 0 && t < SEQ) {
                jl[nj] = l; jt[nj] = t;
                jnw[nj] = (l == 0) ? 1 : 4;
                jnp[nj] = jnw[nj] + ((t > 0) ? 4 : 0);
                tot += jnp[nj];
                nj++;
            }
        }

        // issue loads for flattened phase idx
        auto issue = [&](int idx) {
            int j = 0, p = idx;
            while (p >= jnp[j]) { p -= jnp[j]; j++; }
            int l = jl[j], t = jt[j];
            const uint8_t* Asrc; int lda;
            const uint8_t* Bsrc = nullptr; int ldb = 0;
            if (p < jnw[j]) {                          // W phase
                if (l == 0) {
                    Asrc = g_X0 + ((size_t)t * BATCH + rowBase) * EMBP;   lda = EMBP;
                    Bsrc = g_W0t + (size_t)colBase * EMBP;                ldb = EMBP;
                } else {
                    Asrc = g_H[l-1] + ((size_t)t * BATCH + rowBase) * 512 + p * 128; lda = 512;
                    Bsrc = g_Wt[l-1] + (size_t)colBase * 512 + p * 128;              ldb = 512;
                }
            } else {                                   // U phase
                int uc = p - jnw[j];
                Asrc = g_H[l] + ((size_t)(t - 1) * BATCH + rowBase) * 512 + uc * 128;
                lda = 512;
            }
            uint32_t ab = sb + SB_A + (idx % 3) * 16384;
            #pragma unroll
            for (int i = 0; i < 4; i++) {
                int u = tid + i * 256;
                int row = u >> 3, g = (u & 7) << 4;
                cpa16(ab + row * 128 + SWZ(g, row), Asrc + (size_t)row * lda + g);
            }
            if (Bsrc) {
                uint32_t bb = sb + SB_W + (idx % 3) * 8192;
                #pragma unroll
                for (int i = 0; i < 2; i++) {
                    int u = tid + i * 256;
                    int row = u >> 3, g = (u & 7) << 4;
                    cpa16(bb + row * 128 + SWZ(g, row), Bsrc + (size_t)row * ldb + g);
                }
            }
            cp_commit();
        };

        if (tot > 0) issue(0);
        if (tot > 1) issue(1);

        int j = 0, pin = 0;
        for (int idx = 0; idx < tot; ++idx) {
            if (idx + 2 < tot) { issue(idx + 2); cp_wait<2>(); }
            else if (idx + 1 < tot) cp_wait<1>();
            else cp_wait<0>();
            __syncthreads();

            const bool isW = (pin < jnw[j]);
            const int l = jl[j];
            const int uc = pin - jnw[j];
            const uint32_t ab = sb + SB_A + (idx % 3) * 16384;
            uint32_t bb; int shift; uint32_t bc0;
            if (isW) { bb = sb + SB_W + (idx % 3) * 8192; shift = 7; bc0 = 0; }
            else     { bb = sb + SB_U + l * 32768;        shift = 9; bc0 = uc * 128; }

            #pragma unroll
            for (int k = 0; k < 4; k++) {
                uint32_t a[2][4];
                #pragma unroll
                for (int mt = 0; mt < 2; mt++) {
                    uint32_t row = wm * 32 + mt * 16 + (lane & 15);
                    uint32_t cb  = k * 32 + ((lane >> 4) << 4);
                    ldsm4(a[mt], ab + row * 128 + SWZ(cb, row));
                }
                #pragma unroll
                for (int g = 0; g < 2; g++) {
                    uint32_t row = wn * 32 + g * 16 + (lane & 7) + ((lane >> 4) << 3);
                    uint32_t cb  = bc0 + k * 32 + (((lane >> 3) & 1) << 4);
                    uint32_t b[4];
                    ldsm4(b, bb + (row << shift) + SWZ(cb, row));
                    mma_fp8(acc[0][2 * g],     a[0], b[0], b[1]);
                    mma_fp8(acc[1][2 * g],     a[1], b[0], b[1]);
                    mma_fp8(acc[0][2 * g + 1], a[0], b[2], b[3]);
                    mma_fp8(acc[1][2 * g + 1], a[1], b[2], b[3]);
                }
            }
            __syncthreads();   // before ring buffer (idx%3) is rewritten by issue(idx+3)

            if (++pin == jnp[j]) {
                // ---- epilogue for job j: h = tanh(acc*DESCALE + b), store fp8*HSCALE ----
                const int t = jt[j];
                const float* bp = bias[l];
                uint8_t* Hl = g_H[l];
                #pragma unroll
                for (int mt = 0; mt < 2; mt++)
                    #pragma unroll
                    for (int nf = 0; nf < 4; nf++) {
                        int cc = colBase + c0l + nf * 8;
                        float bb0 = bp[cc], bb1 = bp[cc + 1];
                        float p0 = tanhf(acc[mt][nf][0] * DESCALE + bb0);
                        float p1 = tanhf(acc[mt][nf][1] * DESCALE + bb1);
                        float p2 = tanhf(acc[mt][nf][2] * DESCALE + bb0);
                        float p3 = tanhf(acc[mt][nf][3] * DESCALE + bb1);
                        size_t base = ((size_t)t * BATCH + r0 + mt * 16) * 512 + cc;
                        *(unsigned short*)(Hl + base) =
                            __nv_cvt_float2_to_fp8x2(make_float2(p0 * HSCALE, p1 * HSCALE),
                                                     __NV_SATFINITE, __NV_E4M3);
                        *(unsigned short*)(Hl + base + 8 * 512) =
                            __nv_cvt_float2_to_fp8x2(make_float2(p2 * HSCALE, p3 * HSCALE),
                                                     __NV_SATFINITE, __NV_E4M3);
                        acc[mt][nf][0] = acc[mt][nf][1] = 0.0f;
                        acc[mt][nf][2] = acc[mt][nf][3] = 0.0f;
                    }
                j++; pin = 0;
            }
        }

        // ---- row-group barrier (8 column-CTAs) between wavefront steps ----
        if (s < MAXS - 1) {
            __syncthreads();
            if (tid == 0) {
                unsigned* ctr = &g_bar2[ygrp][s];
                asm volatile("red.release.gpu.global.add.u32 [%0], %1;"
                             :: "l"(ctr), "r"(1u) : "memory");
                unsigned v;
                do {
                    asm volatile("ld.acquire.gpu.global.u32 %0, [%1];"
                                 : "=r"(v) : "l"(ctr) : "memory");
                } while (v < (unsigned)RGRIDX);
            }
            __syncthreads();
        }
    }
}

// ---------------- head ----------------
__global__ void final_kernel(const float* __restrict__ Wo, const float* __restrict__ bo,
                             float* __restrict__ out) {
    int gw   = (blockIdx.x * blockDim.x + threadIdx.x) >> 5;
    int lane = threadIdx.x & 31;
    if (gw >= BATCH) return;
    const uint8_t* h = g_H[3] + ((size_t)(SEQ - 1) * BATCH + gw) * 512;
    float s = 0.0f;
    for (int k = lane; k < UNITS; k += 32) {
        __half_raw hr = __nv_cvt_fp8_to_halfraw(h[k], __NV_E4M3);
        s += __half2float(*(__half*)&hr) * Wo[k];
    }
    #pragma unroll
    for (int o = 16; o; o >>= 1) s += __shfl_xor_sync(0xffffffffu, s, o);
    if (lane == 0) out[gw] = 1.0f / (1.0f + expf(-(s * (1.0f / HSCALE) + bo[0])));
}

// ---------------- host ----------------
extern "C" void kernel_launch(void* const* d_in, const int* in_sizes, int n_in,
                              void* d_out, int out_size) {
    const int*   tokens = (const int*)d_in[0];
    const float* emb    = (const float*)d_in[1];
    const float* W[4]  = {(const float*)d_in[2], (const float*)d_in[5],
                          (const float*)d_in[8], (const float*)d_in[11]};
    const float* U[4]  = {(const float*)d_in[3], (const float*)d_in[6],
                          (const float*)d_in[9], (const float*)d_in[12]};
    const float* bv[4] = {(const float*)d_in[4], (const float*)d_in[7],
                          (const float*)d_in[10], (const float*)d_in[13]};
    const float* Wo = (const float*)d_in[14];
    const float* bo = (const float*)d_in[15];
    float* out = (float*)d_out;

    cudaFuncSetAttribute(wave_kernel, cudaFuncAttributeMaxDynamicSharedMemorySize, SM_TOTAL);

    // launch order fixed so ncu (-s 5 -c 1) profiles wave_kernel (launch #6)
    cvtW_kernel<<<(512 * 128 + 3 * 512 * 512 + 255) / 256, 256>>>(W[0], W[1], W[2], W[3]);
    cvtU_kernel<<<(4 * 512 * 512 + 255) / 256, 256>>>(U[0], U[1], U[2], U[3]);
    embed_kernel<<<(BT * EMBP + 255) / 256, 256>>>(tokens, emb);
    zero0_kernel<<<1, 256>>>();
    zero1_kernel<<<1, 256>>>();

    wave_kernel<<<NCTA, 256, SM_TOTAL>>>(bv[0], bv[1], bv[2], bv[3]);

    final_kernel<<<BATCH / 8, 256>>>(Wo, bo, out);
}

// round 10
// speedup vs baseline: 1.0402x; 1.0402x over previous
#include <cuda_runtime.h>
#include <cuda_bf16.h>
#include <cuda_fp16.h>
#include <cuda_fp8.h>
#include <cstdint>

#define VOCAB 10000
#define EMBD 100
#define EMBP 128          // EMB padded to one full 128B chunk
#define SEQ 80
#define UNITS 512
#define BATCH 2048
#define BT (BATCH*SEQ)    // 163840

// fp8 scaling: keep values out of e4m3 subnormal range
#define HSCALE 256.0f
#define WSCALE 64.0f
#define DESCALE (1.0f/(HSCALE*WSCALE))

#define RGRIDX 8
#define RGRIDY 16

#define CH 128            // K bytes per chunk
#define AROW 144          // smem row pitch (128+16 pad, conflict-free ldmatrix)
#define ABUF (128*AROW)   // 18432 B
#define UROW 528          // U smem row pitch (512+16)
#define XW_SMEM (6*ABUF)              // 110592
#define R_SMEM (64*UROW + 4*ABUF)     // 107520

// ---------------- device scratch; t-major rows ----------------
__device__ __align__(16) uint8_t        g_X0[(size_t)BT * EMBP];   // fp8*HSCALE
__device__ __align__(16) uint8_t        g_X [(size_t)BT * UNITS];  // h, fp8*HSCALE
__device__ __align__(16) __nv_bfloat16  g_XW[(size_t)BT * UNITS];  // projection, bf16
__device__ __align__(16) uint8_t        g_W1t[UNITS * EMBP];       // W1^T fp8*WSCALE
__device__ __align__(16) uint8_t        g_Wt [3][UNITS * UNITS];
__device__ __align__(16) uint8_t        g_Ut [4][UNITS * UNITS];
__device__ unsigned g_bar[4][RGRIDY][SEQ];

// ---------------- PTX helpers ----------------
__device__ __forceinline__ uint32_t smaddr(const void* p) {
    return (uint32_t)__cvta_generic_to_shared(p);
}
__device__ __forceinline__ void cpa16(uint32_t dst, const void* src) {
    asm volatile("cp.async.cg.shared.global [%0], [%1], 16;\n" :: "r"(dst), "l"(src));
}
__device__ __forceinline__ void cp_commit() { asm volatile("cp.async.commit_group;\n"); }
template<int N> __device__ __forceinline__ void cp_wait() {
    asm volatile("cp.async.wait_group %0;\n" :: "n"(N));
}
__device__ __forceinline__ void ldsm4(uint32_t (&r)[4], uint32_t addr) {
    asm volatile("ldmatrix.sync.aligned.m8n8.x4.shared.b16 {%0,%1,%2,%3}, [%4];\n"
                 : "=r"(r[0]), "=r"(r[1]), "=r"(r[2]), "=r"(r[3]) : "r"(addr));
}
__device__ __forceinline__ void mma_fp8(float (&d)[4], const uint32_t (&a)[4],
                                        uint32_t b0, uint32_t b1) {
    asm volatile("mma.sync.aligned.m16n8k32.row.col.f32.e4m3.e4m3.f32 "
                 "{%0,%1,%2,%3}, {%4,%5,%6,%7}, {%8,%9}, {%0,%1,%2,%3};\n"
                 : "+f"(d[0]), "+f"(d[1]), "+f"(d[2]), "+f"(d[3])
                 : "r"(a[0]), "r"(a[1]), "r"(a[2]), "r"(a[3]), "r"(b0), "r"(b1));
}
__device__ __forceinline__ uint8_t to_fp8(float v) {
    return (uint8_t)__nv_cvt_float_to_fp8(v, __NV_SATFINITE, __NV_E4M3);
}

// ---------------- prep kernels (2 launches so rnn_fp8 lands at launch #4) --------
__global__ void cvtAll_kernel(
    const float* __restrict__ W1, const float* __restrict__ W2,
    const float* __restrict__ W3, const float* __restrict__ W4,
    const float* __restrict__ U1, const float* __restrict__ U2,
    const float* __restrict__ U3, const float* __restrict__ U4)
{
    int i = blockIdx.x * blockDim.x + threadIdx.x;
    if (i < 512 * 128) {                        // W1 -> [512n][128k]
        int n = i >> 7, k = i & 127;
        g_W1t[i] = to_fp8(k < EMBD ? W1[(size_t)k * 512 + n] * WSCALE : 0.0f);
        return;
    }
    i -= 512 * 128;
    if (i < 3 * 512 * 512) {                    // W2..4 -> [512n][512k]
        int m = i >> 18, r = i & (512 * 512 - 1);
        int n = r >> 9, k = r & 511;
        const float* Wm = (m == 0) ? W2 : (m == 1) ? W3 : W4;
        g_Wt[m][r] = to_fp8(Wm[(size_t)k * 512 + n] * WSCALE);
        return;
    }
    i -= 3 * 512 * 512;
    if (i >= 4 * 512 * 512) return;             // U1..4
    int m = i >> 18, r = i & (512 * 512 - 1);
    int n = r >> 9, k = r & 511;
    const float* Um = (m == 0) ? U1 : (m == 1) ? U2 : (m == 2) ? U3 : U4;
    g_Ut[m][r] = to_fp8(Um[(size_t)k * 512 + n] * WSCALE);
}

__global__ void embed_zero_kernel(const int* __restrict__ tokens,
                                  const float* __restrict__ emb) {
    int i = blockIdx.x * blockDim.x + threadIdx.x;
    if (i < 4 * RGRIDY * SEQ) ((unsigned*)g_bar)[i] = 0u;
    if (i >= BT * EMBP) return;
    int r = i >> 7, k = i & 127;
    int t = r / BATCH, b = r - t * BATCH;
    float v = (k < EMBD) ? emb[(size_t)tokens[b * SEQ + t] * EMBD + k] * HSCALE : 0.0f;
    g_X0[i] = to_fp8(v);
}

// ================= XW GEMM (fp8): C = (A @ Bt^T)*DESCALE + bias, bf16 out =======
__global__ __launch_bounds__(256, 1) void gemm_fp8(
    const uint8_t* __restrict__ A, int lda,
    const uint8_t* __restrict__ Bt, int ldb,
    const float* __restrict__ bias,
    __nv_bfloat16* __restrict__ C, int nchunk)
{
    extern __shared__ __align__(128) uint8_t smbuf[];
    const uint32_t sb = smaddr(smbuf);
    const uint32_t BOFF = 3 * ABUF;

    const int tid = threadIdx.x, lane = tid & 31, wid = tid >> 5;
    const int wm = wid & 3, wn = wid >> 2;
    const int rowBase = blockIdx.y * 128, colBase = blockIdx.x * 128;

    auto loadAB = [&](int c) {
        const int buf = c % 3;
        const uint8_t* Ab = A  + (size_t)rowBase * lda + c * CH;
        const uint8_t* Bb = Bt + (size_t)colBase * ldb + c * CH;
        #pragma unroll
        for (int i = 0; i < 4; i++) {
            int u = tid + i * 256;
            int row = u >> 3, c16 = (u & 7) * 16;
            cpa16(sb + buf * ABUF + row * AROW + c16, Ab + (size_t)row * lda + c16);
            cpa16(sb + BOFF + buf * ABUF + row * AROW + c16, Bb + (size_t)row * ldb + c16);
        }
        cp_commit();
    };

    loadAB(0);
    if (nchunk > 1) loadAB(1);

    float acc[2][8][4];
    #pragma unroll
    for (int mt = 0; mt < 2; mt++)
        #pragma unroll
        for (int nf = 0; nf < 8; nf++)
            #pragma unroll
            for (int j = 0; j < 4; j++) acc[mt][nf][j] = 0.0f;

    for (int c = 0; c < nchunk; ++c) {
        if (c + 1 < nchunk) cp_wait<1>(); else cp_wait<0>();
        __syncthreads();
        if (c + 2 < nchunk) loadAB(c + 2);
        const uint32_t sa  = sb + (c % 3) * ABUF;
        const uint32_t sbb = sb + BOFF + (c % 3) * ABUF;
        #pragma unroll
        for (int k = 0; k < 4; k++) {
            uint32_t a[2][4];
            #pragma unroll
            for (int mt = 0; mt < 2; mt++)
                ldsm4(a[mt], sa + (uint32_t)(wm * 32 + mt * 16 + (lane & 15)) * AROW
                                + k * 32 + ((lane >> 4) << 4));
            #pragma unroll
            for (int g = 0; g < 4; g++) {
                uint32_t b[4];
                ldsm4(b, sbb + (uint32_t)(wn * 64 + g * 16 + (lane & 7)
                                          + ((lane >> 4) << 3)) * AROW
                             + k * 32 + (((lane >> 3) & 1) << 4));
                mma_fp8(acc[0][2 * g],     a[0], b[0], b[1]);
                mma_fp8(acc[1][2 * g],     a[1], b[0], b[1]);
                mma_fp8(acc[0][2 * g + 1], a[0], b[2], b[3]);
                mma_fp8(acc[1][2 * g + 1], a[1], b[2], b[3]);
            }
        }
        __syncthreads();
    }

    const int r0 = rowBase + wm * 32 + (lane >> 2);
    const int c0 = colBase + wn * 64 + (lane & 3) * 2;
    #pragma unroll
    for (int mt = 0; mt < 2; mt++)
        #pragma unroll
        for (int nf = 0; nf < 8; nf++) {
            int r = r0 + mt * 16, c = c0 + nf * 8;
            float b0 = bias[c], b1 = bias[c + 1];
            __nv_bfloat162 v0 = __float22bfloat162_rn(
                make_float2(acc[mt][nf][0] * DESCALE + b0, acc[mt][nf][1] * DESCALE + b1));
            __nv_bfloat162 v1 = __float22bfloat162_rn(
                make_float2(acc[mt][nf][2] * DESCALE + b0, acc[mt][nf][3] * DESCALE + b1));
            *(__nv_bfloat162*)(C + (size_t)r * UNITS + c)       = v0;
            *(__nv_bfloat162*)(C + (size_t)(r + 8) * UNITS + c) = v1;
        }
}

// ================= persistent recurrence (fp8) =================
// grid (8,16)=128 CTAs, 1/SM. CTA (x,y): rows [128y..), cols [64x..). U resident.
// Step: issue 4 A-chunks (4 groups) -> progressive-wait mma -> epilogue ->
// one __syncthreads -> tid0 release-arrive -> EVERY warp polls acquire independently.
__global__ __launch_bounds__(256, 1) void rnn_fp8(
    const uint8_t* __restrict__ Ut,
    const __nv_bfloat16* __restrict__ XW,
    uint8_t* __restrict__ X,
    int layer)
{
    extern __shared__ __align__(128) uint8_t smbuf[];
    const uint32_t sb = smaddr(smbuf);
    const uint32_t AOFF = 64 * UROW;

    const int tid = threadIdx.x, lane = tid & 31, wid = tid >> 5;
    const int wm = wid & 3, wn = wid >> 2;
    const int rowBase = blockIdx.y * 128, colBase = blockIdx.x * 64;

    // resident U slice [64 n][512 k]
    #pragma unroll
    for (int i = 0; i < 8; i++) {
        int u = tid + i * 256;
        int row = u >> 5, c16 = (u & 31) * 16;
        cpa16(sb + (uint32_t)row * UROW + c16, Ut + (size_t)(colBase + row) * UNITS + c16);
    }
    cp_commit();
    cp_wait<0>();
    __syncthreads();

    unsigned* barRow = &g_bar[layer][blockIdx.y][0];
    const int r0 = rowBase + wm * 32 + (lane >> 2);
    const int c0 = colBase + wn * 32 + (lane & 3) * 2;

    for (int t = 0; t < SEQ; ++t) {
        if (t > 0) {
            // all 4 A-chunk loads (h_{t-1}) up-front, 4 commit groups
            const uint8_t* Ab = X + ((size_t)(t - 1) * BATCH + rowBase) * UNITS;
            #pragma unroll
            for (int c = 0; c < 4; c++) {
                #pragma unroll
                for (int i = 0; i < 4; i++) {
                    int u = tid + i * 256;
                    int row = u >> 3, c16 = (u & 7) * 16;
                    cpa16(sb + AOFF + c * ABUF + (uint32_t)row * AROW + c16,
                          Ab + (size_t)row * UNITS + c * CH + c16);
                }
                cp_commit();
            }
        }

        // XW fragment prefetch (independent of barrier/loads)
        uint32_t xwv[2][4][2];
        #pragma unroll
        for (int mt = 0; mt < 2; mt++)
            #pragma unroll
            for (int nf = 0; nf < 4; nf++) {
                size_t base = ((size_t)t * BATCH + r0 + mt * 16) * UNITS + c0 + nf * 8;
                xwv[mt][nf][0] = *(const uint32_t*)(XW + base);
                xwv[mt][nf][1] = *(const uint32_t*)(XW + base + 8 * UNITS);
            }

        float acc[2][4][4];
        #pragma unroll
        for (int mt = 0; mt < 2; mt++)
            #pragma unroll
            for (int nf = 0; nf < 4; nf++)
                #pragma unroll
                for (int j = 0; j < 4; j++) acc[mt][nf][j] = 0.0f;

        if (t > 0) {
            #pragma unroll
            for (int c = 0; c < 4; c++) {
                if (c == 0)      cp_wait<3>();
                else if (c == 1) cp_wait<2>();
                else if (c == 2) cp_wait<1>();
                else             cp_wait<0>();
                __syncthreads();
                const uint32_t sa = sb + AOFF + c * ABUF;
                #pragma unroll
                for (int k = 0; k < 4; k++) {
                    uint32_t a[2][4];
                    #pragma unroll
                    for (int mt = 0; mt < 2; mt++)
                        ldsm4(a[mt], sa + (uint32_t)(wm * 32 + mt * 16 + (lane & 15)) * AROW
                                        + k * 32 + ((lane >> 4) << 4));
                    #pragma unroll
                    for (int g = 0; g < 2; g++) {
                        uint32_t b[4];
                        ldsm4(b, sb + (uint32_t)(wn * 32 + g * 16 + (lane & 7)
                                                 + ((lane >> 4) << 3)) * UROW
                                    + c * CH + k * 32 + (((lane >> 3) & 1) << 4));
                        mma_fp8(acc[0][2 * g],     a[0], b[0], b[1]);
                        mma_fp8(acc[1][2 * g],     a[1], b[0], b[1]);
                        mma_fp8(acc[0][2 * g + 1], a[0], b[2], b[3]);
                        mma_fp8(acc[1][2 * g + 1], a[1], b[2], b[3]);
                    }
                }
            }
        }

        // epilogue: h = tanh(acc*DESCALE + XW); store fp8*HSCALE
        #pragma unroll
        for (int mt = 0; mt < 2; mt++)
            #pragma unroll
            for (int nf = 0; nf < 4; nf++) {
                float2 xa = __bfloat1622float2(*(__nv_bfloat162*)&xwv[mt][nf][0]);
                float2 xb = __bfloat1622float2(*(__nv_bfloat162*)&xwv[mt][nf][1]);
                float p0 = tanhf(acc[mt][nf][0] * DESCALE + xa.x);
                float p1 = tanhf(acc[mt][nf][1] * DESCALE + xa.y);
                float p2 = tanhf(acc[mt][nf][2] * DESCALE + xb.x);
                float p3 = tanhf(acc[mt][nf][3] * DESCALE + xb.y);
                size_t base = ((size_t)t * BATCH + r0 + mt * 16) * UNITS + c0 + nf * 8;
                *(unsigned short*)(X + base) =
                    __nv_cvt_float2_to_fp8x2(make_float2(p0 * HSCALE, p1 * HSCALE),
                                             __NV_SATFINITE, __NV_E4M3);
                *(unsigned short*)(X + base + 8 * UNITS) =
                    __nv_cvt_float2_to_fp8x2(make_float2(p2 * HSCALE, p3 * HSCALE),
                                             __NV_SATFINITE, __NV_E4M3);
            }

        // inter-CTA barrier: one syncthreads, tid0 release-arrives, all warps poll
        if (t < SEQ - 1) {
            __syncthreads();                     // orders all stores before arrival
            unsigned* ctr = barRow + t;
            if (tid == 0)
                asm volatile("red.release.gpu.global.add.u32 [%0], %1;"
                             :: "l"(ctr), "r"(1u) : "memory");
            if (lane == 0) {                     // each warp polls independently
                unsigned v;
                do {
                    asm volatile("ld.acquire.gpu.global.u32 %0, [%1];"
                                 : "=r"(v) : "l"(ctr) : "memory");
                } while (v < (unsigned)RGRIDX);
            }
            __syncwarp();
            // warps re-converge at the per-chunk __syncthreads of the next step
        }
    }
}

// ---------------- head ----------------
__global__ void final_kernel(const uint8_t* __restrict__ X,
                             const float* __restrict__ Wo, const float* __restrict__ bo,
                             float* __restrict__ out) {
    int gw   = (blockIdx.x * blockDim.x + threadIdx.x) >> 5;
    int lane = threadIdx.x & 31;
    if (gw >= BATCH) return;
    const uint8_t* h = X + ((size_t)(SEQ - 1) * BATCH + gw) * UNITS;
    float s = 0.0f;
    for (int k = lane; k < UNITS; k += 32) {
        __half_raw hr = __nv_cvt_fp8_to_halfraw(h[k], __NV_E4M3);
        s += __half2float(*(__half*)&hr) * Wo[k];
    }
    #pragma unroll
    for (int o = 16; o; o >>= 1) s += __shfl_xor_sync(0xffffffffu, s, o);
    if (lane == 0) out[gw] = 1.0f / (1.0f + expf(-(s * (1.0f / HSCALE) + bo[0])));
}

// ---------------- host ----------------
extern "C" void kernel_launch(void* const* d_in, const int* in_sizes, int n_in,
                              void* d_out, int out_size) {
    const int*   tokens = (const int*)d_in[0];
    const float* emb    = (const float*)d_in[1];
    const float* W[4]  = {(const float*)d_in[2], (const float*)d_in[5],
                          (const float*)d_in[8], (const float*)d_in[11]};
    const float* U[4]  = {(const float*)d_in[3], (const float*)d_in[6],
                          (const float*)d_in[9], (const float*)d_in[12]};
    const float* bv[4] = {(const float*)d_in[4], (const float*)d_in[7],
                          (const float*)d_in[10], (const float*)d_in[13]};
    const float* Wo = (const float*)d_in[14];
    const float* bo = (const float*)d_in[15];
    float* out = (float*)d_out;

    uint8_t *X0p, *Xp, *W1tp, *Wtp, *Utp;
    __nv_bfloat16* XWp;
    cudaGetSymbolAddress((void**)&X0p,  g_X0);
    cudaGetSymbolAddress((void**)&Xp,   g_X);
    cudaGetSymbolAddress((void**)&XWp,  g_XW);
    cudaGetSymbolAddress((void**)&W1tp, g_W1t);
    cudaGetSymbolAddress((void**)&Wtp,  g_Wt);
    cudaGetSymbolAddress((void**)&Utp,  g_Ut);

    cudaFuncSetAttribute(gemm_fp8, cudaFuncAttributeMaxDynamicSharedMemorySize, XW_SMEM);
    cudaFuncSetAttribute(rnn_fp8,  cudaFuncAttributeMaxDynamicSharedMemorySize, R_SMEM);

    // launch #1, #2: prep (so launch #3 = gemm L1, launch #4 = rnn L1 for ncu skip-3)
    cvtAll_kernel<<<(512*128 + 7*512*512 + 255) / 256, 256>>>(
        W[0], W[1], W[2], W[3], U[0], U[1], U[2], U[3]);
    embed_zero_kernel<<<(BT * EMBP + 255) / 256, 256>>>(tokens, emb);

    for (int l = 0; l < 4; l++) {
        if (l == 0) {
            gemm_fp8<<<dim3(UNITS / 128, BT / 128), 256, XW_SMEM>>>(
                X0p, EMBP, W1tp, EMBP, bv[0], XWp, 1);
        } else {
            gemm_fp8<<<dim3(UNITS / 128, BT / 128), 256, XW_SMEM>>>(
                Xp, UNITS, Wtp + (size_t)(l - 1) * UNITS * UNITS, UNITS,
                bv[l], XWp, 4);
        }
        rnn_fp8<<<dim3(RGRIDX, RGRIDY), 256, R_SMEM>>>(
            Utp + (size_t)l * UNITS * UNITS, XWp, Xp, l);
    }

    final_kernel<<<BATCH / 8, 256>>>(Xp, Wo, bo, out);
}

// round 12
// speedup vs baseline: 1.0465x; 1.0061x over previous
#include <cuda_runtime.h>
#include <cuda_bf16.h>
#include <cuda_fp16.h>
#include <cuda_fp8.h>
#include <cstdint>

#define VOCAB 10000
#define EMBD 100
#define EMBP 128          // EMB padded to one full 128B chunk
#define SEQ 80
#define UNITS 512
#define BATCH 2048
#define BT (BATCH*SEQ)    // 163840

// fp8 scaling: keep values out of e4m3 subnormal range
#define HSCALE 256.0f
#define WSCALE 64.0f
#define DESCALE (1.0f/(HSCALE*WSCALE))

#define RGRIDX 8
#define RGRIDY 16

#define CH 128            // K bytes per chunk
#define AROW 144          // smem row pitch (128+16 pad, conflict-free ldmatrix)
#define ABUF (128*AROW)   // 18432 B
#define UROW 528          // U smem row pitch (512+16)
#define XW_SMEM (6*ABUF)              // 110592
#define R_SMEM (64*UROW + 4*ABUF)     // 107520

// ---------------- device scratch; t-major rows ----------------
__device__ __align__(16) uint8_t        g_X0[(size_t)BT * EMBP];   // fp8*HSCALE
__device__ __align__(16) uint8_t        g_X [(size_t)BT * UNITS];  // h, fp8*HSCALE
__device__ __align__(16) __nv_bfloat16  g_XW[(size_t)BT * UNITS];  // projection, bf16
__device__ __align__(16) uint8_t        g_W1t[UNITS * EMBP];       // W1^T fp8*WSCALE
__device__ __align__(16) uint8_t        g_Wt [3][UNITS * UNITS];
__device__ __align__(16) uint8_t        g_Ut [4][UNITS * UNITS];
__device__ unsigned g_bar[4][RGRIDY][SEQ];

// ---------------- PTX helpers ----------------
__device__ __forceinline__ uint32_t smaddr(const void* p) {
    return (uint32_t)__cvta_generic_to_shared(p);
}
__device__ __forceinline__ void cpa16(uint32_t dst, const void* src) {
    asm volatile("cp.async.cg.shared.global [%0], [%1], 16;\n" :: "r"(dst), "l"(src));
}
__device__ __forceinline__ void cp_commit() { asm volatile("cp.async.commit_group;\n"); }
template<int N> __device__ __forceinline__ void cp_wait() {
    asm volatile("cp.async.wait_group %0;\n" :: "n"(N));
}
__device__ __forceinline__ void ldsm4(uint32_t (&r)[4], uint32_t addr) {
    asm volatile("ldmatrix.sync.aligned.m8n8.x4.shared.b16 {%0,%1,%2,%3}, [%4];\n"
                 : "=r"(r[0]), "=r"(r[1]), "=r"(r[2]), "=r"(r[3]) : "r"(addr));
}
__device__ __forceinline__ void mma_fp8(float (&d)[4], const uint32_t (&a)[4],
                                        uint32_t b0, uint32_t b1) {
    asm volatile("mma.sync.aligned.m16n8k32.row.col.f32.e4m3.e4m3.f32 "
                 "{%0,%1,%2,%3}, {%4,%5,%6,%7}, {%8,%9}, {%0,%1,%2,%3};\n"
                 : "+f"(d[0]), "+f"(d[1]), "+f"(d[2]), "+f"(d[3])
                 : "r"(a[0]), "r"(a[1]), "r"(a[2]), "r"(a[3]), "r"(b0), "r"(b1));
}
__device__ __forceinline__ uint8_t to_fp8(float v) {
    return (uint8_t)__nv_cvt_float_to_fp8(v, __NV_SATFINITE, __NV_E4M3);
}
// fast tanh: 1 - 2/(e^{2x}+1); saturates to +-1 for large |x| (no NaN)
__device__ __forceinline__ float ftanh(float x) {
    return 1.0f - __fdividef(2.0f, __expf(2.0f * x) + 1.0f);
}

// ---------------- prep kernels (2 launches; rnn L1 stays at ncu's launch #4) -----
__global__ void cvtAll_kernel(
    const float* __restrict__ W1, const float* __restrict__ W2,
    const float* __restrict__ W3, const float* __restrict__ W4,
    const float* __restrict__ U1, const float* __restrict__ U2,
    const float* __restrict__ U3, const float* __restrict__ U4)
{
    int i = blockIdx.x * blockDim.x + threadIdx.x;
    if (i < 512 * 128) {
        int n = i >> 7, k = i & 127;
        g_W1t[i] = to_fp8(k < EMBD ? W1[(size_t)k * 512 + n] * WSCALE : 0.0f);
        return;
    }
    i -= 512 * 128;
    if (i < 3 * 512 * 512) {
        int m = i >> 18, r = i & (512 * 512 - 1);
        int n = r >> 9, k = r & 511;
        const float* Wm = (m == 0) ? W2 : (m == 1) ? W3 : W4;
        g_Wt[m][r] = to_fp8(Wm[(size_t)k * 512 + n] * WSCALE);
        return;
    }
    i -= 3 * 512 * 512;
    if (i >= 4 * 512 * 512) return;
    int m = i >> 18, r = i & (512 * 512 - 1);
    int n = r >> 9, k = r & 511;
    const float* Um = (m == 0) ? U1 : (m == 1) ? U2 : (m == 2) ? U3 : U4;
    g_Ut[m][r] = to_fp8(Um[(size_t)k * 512 + n] * WSCALE);
}

__global__ void embed_zero_kernel(const int* __restrict__ tokens,
                                  const float* __restrict__ emb) {
    int i = blockIdx.x * blockDim.x + threadIdx.x;
    if (i < 4 * RGRIDY * SEQ) ((unsigned*)g_bar)[i] = 0u;
    if (i >= BT * EMBP) return;
    int r = i >> 7, k = i & 127;
    int t = r / BATCH, b = r - t * BATCH;
    float v = (k < EMBD) ? emb[(size_t)tokens[b * SEQ + t] * EMBD + k] * HSCALE : 0.0f;
    g_X0[i] = to_fp8(v);
}

// ================= XW GEMM (fp8): C = (A @ Bt^T)*DESCALE + bias, bf16 out =======
__global__ __launch_bounds__(256, 1) void gemm_fp8(
    const uint8_t* __restrict__ A, int lda,
    const uint8_t* __restrict__ Bt, int ldb,
    const float* __restrict__ bias,
    __nv_bfloat16* __restrict__ C, int nchunk)
{
    extern __shared__ __align__(128) uint8_t smbuf[];
    const uint32_t sb = smaddr(smbuf);
    const uint32_t BOFF = 3 * ABUF;

    const int tid = threadIdx.x, lane = tid & 31, wid = tid >> 5;
    const int wm = wid & 3, wn = wid >> 2;
    const int rowBase = blockIdx.y * 128, colBase = blockIdx.x * 128;

    auto loadAB = [&](int c) {
        const int buf = c % 3;
        const uint8_t* Ab = A  + (size_t)rowBase * lda + c * CH;
        const uint8_t* Bb = Bt + (size_t)colBase * ldb + c * CH;
        #pragma unroll
        for (int i = 0; i < 4; i++) {
            int u = tid + i * 256;
            int row = u >> 3, c16 = (u & 7) * 16;
            cpa16(sb + buf * ABUF + row * AROW + c16, Ab + (size_t)row * lda + c16);
            cpa16(sb + BOFF + buf * ABUF + row * AROW + c16, Bb + (size_t)row * ldb + c16);
        }
        cp_commit();
    };

    loadAB(0);
    if (nchunk > 1) loadAB(1);

    float acc[2][8][4];
    #pragma unroll
    for (int mt = 0; mt < 2; mt++)
        #pragma unroll
        for (int nf = 0; nf < 8; nf++)
            #pragma unroll
            for (int j = 0; j < 4; j++) acc[mt][nf][j] = 0.0f;

    for (int c = 0; c < nchunk; ++c) {
        if (c + 1 < nchunk) cp_wait<1>(); else cp_wait<0>();
        __syncthreads();
        if (c + 2 < nchunk) loadAB(c + 2);
        const uint32_t sa  = sb + (c % 3) * ABUF;
        const uint32_t sbb = sb + BOFF + (c % 3) * ABUF;
        #pragma unroll
        for (int k = 0; k < 4; k++) {
            uint32_t a[2][4];
            #pragma unroll
            for (int mt = 0; mt < 2; mt++)
                ldsm4(a[mt], sa + (uint32_t)(wm * 32 + mt * 16 + (lane & 15)) * AROW
                                + k * 32 + ((lane >> 4) << 4));
            #pragma unroll
            for (int g = 0; g < 4; g++) {
                uint32_t b[4];
                ldsm4(b, sbb + (uint32_t)(wn * 64 + g * 16 + (lane & 7)
                                          + ((lane >> 4) << 3)) * AROW
                             + k * 32 + (((lane >> 3) & 1) << 4));
                mma_fp8(acc[0][2 * g],     a[0], b[0], b[1]);
                mma_fp8(acc[1][2 * g],     a[1], b[0], b[1]);
                mma_fp8(acc[0][2 * g + 1], a[0], b[2], b[3]);
                mma_fp8(acc[1][2 * g + 1], a[1], b[2], b[3]);
            }
        }
        __syncthreads();
    }

    const int r0 = rowBase + wm * 32 + (lane >> 2);
    const int c0 = colBase + wn * 64 + (lane & 3) * 2;
    #pragma unroll
    for (int mt = 0; mt < 2; mt++)
        #pragma unroll
        for (int nf = 0; nf < 8; nf++) {
            int r = r0 + mt * 16, c = c0 + nf * 8;
            float b0 = bias[c], b1 = bias[c + 1];
            __nv_bfloat162 v0 = __float22bfloat162_rn(
                make_float2(acc[mt][nf][0] * DESCALE + b0, acc[mt][nf][1] * DESCALE + b1));
            __nv_bfloat162 v1 = __float22bfloat162_rn(
                make_float2(acc[mt][nf][2] * DESCALE + b0, acc[mt][nf][3] * DESCALE + b1));
            *(__nv_bfloat162*)(C + (size_t)r * UNITS + c)       = v0;
            *(__nv_bfloat162*)(C + (size_t)(r + 8) * UNITS + c) = v1;
        }
}

// ================= persistent recurrence (fp8, 512 threads / 16 warps) =========
// grid (8,16)=128 CTAs, 1/SM. CTA (x,y): rows [128y..), cols [64x..). U resident.
// 16 warps: wm=wid&7 (8 x 16-row strips), wn=wid>>3 (2 x 32-col). 64 mma/warp/step.
__global__ __launch_bounds__(512, 1) void rnn_fp8(
    const uint8_t* __restrict__ Ut,
    const __nv_bfloat16* __restrict__ XW,
    uint8_t* __restrict__ X,
    int layer)
{
    extern __shared__ __align__(128) uint8_t smbuf[];
    const uint32_t sb = smaddr(smbuf);
    const uint32_t AOFF = 64 * UROW;

    const int tid = threadIdx.x, lane = tid & 31, wid = tid >> 5;
    const int wm = wid & 7, wn = wid >> 3;
    const int rowBase = blockIdx.y * 128, colBase = blockIdx.x * 64;

    // resident U slice [64 n][512 k]
    #pragma unroll
    for (int i = 0; i < 4; i++) {
        int u = tid + i * 512;
        int row = u >> 5, c16 = (u & 31) * 16;
        cpa16(sb + (uint32_t)row * UROW + c16, Ut + (size_t)(colBase + row) * UNITS + c16);
    }
    cp_commit();
    cp_wait<0>();
    __syncthreads();

    unsigned* barRow = &g_bar[layer][blockIdx.y][0];
    const int r0 = rowBase + wm * 16 + (lane >> 2);
    const int c0 = colBase + wn * 32 + (lane & 3) * 2;

    // loop-invariant ldsm/ldst base addresses
    const uint32_t aBase = sb + AOFF + (uint32_t)(wm * 16 + (lane & 15)) * AROW
                         + ((lane >> 4) << 4);
    const uint32_t bRow0 = (uint32_t)(wn * 32 + (lane & 7) + ((lane >> 4) << 3));
    const uint32_t bBase = sb + (((lane >> 3) & 1) << 4);
    const uint32_t ldRow = (tid >> 3), ldCol = (tid & 7) * 16;   // A-tile load slot

    for (int t = 0; t < SEQ; ++t) {
        if (t > 0) {
            // all 4 A-chunk loads (h_{t-1}) up-front, 4 commit groups; 2 granules/thread
            const uint8_t* Ab = X + ((size_t)(t - 1) * BATCH + rowBase) * UNITS;
            #pragma unroll
            for (int c = 0; c < 4; c++) {
                #pragma unroll
                for (int i = 0; i < 2; i++) {
                    uint32_t row = ldRow + i * 64;
                    cpa16(sb + AOFF + c * ABUF + row * AROW + ldCol,
                          Ab + (size_t)row * UNITS + c * CH + ldCol);
                }
                cp_commit();
            }
        }

        // XW fragment prefetch
        uint32_t xwv[4][2];
        #pragma unroll
        for (int nf = 0; nf < 4; nf++) {
            size_t base = ((size_t)t * BATCH + r0) * UNITS + c0 + nf * 8;
            xwv[nf][0] = *(const uint32_t*)(XW + base);
            xwv[nf][1] = *(const uint32_t*)(XW + base + 8 * UNITS);
        }

        float acc[4][4];
        #pragma unroll
        for (int nf = 0; nf < 4; nf++)
            #pragma unroll
            for (int j = 0; j < 4; j++) acc[nf][j] = 0.0f;

        if (t > 0) {
            #pragma unroll
            for (int c = 0; c < 4; c++) {
                if (c == 0)      cp_wait<3>();
                else if (c == 1) cp_wait<2>();
                else if (c == 2) cp_wait<1>();
                else             cp_wait<0>();
                __syncthreads();
                #pragma unroll
                for (int k = 0; k < 4; k++) {
                    uint32_t a[4];
                    ldsm4(a, aBase + c * ABUF + k * 32);
                    #pragma unroll
                    for (int g = 0; g < 2; g++) {
                        uint32_t b[4];
                        ldsm4(b, bBase + (bRow0 + g * 16) * UROW + c * CH + k * 32);
                        mma_fp8(acc[2 * g],     a, b[0], b[1]);
                        mma_fp8(acc[2 * g + 1], a, b[2], b[3]);
                    }
                }
            }
        }

        // epilogue: h = tanh(acc*DESCALE + XW); store fp8*HSCALE
        #pragma unroll
        for (int nf = 0; nf < 4; nf++) {
            float2 xa = __bfloat1622float2(*(__nv_bfloat162*)&xwv[nf][0]);
            float2 xb = __bfloat1622float2(*(__nv_bfloat162*)&xwv[nf][1]);
            float p0 = ftanh(acc[nf][0] * DESCALE + xa.x);
            float p1 = ftanh(acc[nf][1] * DESCALE + xa.y);
            float p2 = ftanh(acc[nf][2] * DESCALE + xb.x);
            float p3 = ftanh(acc[nf][3] * DESCALE + xb.y);
            size_t base = ((size_t)t * BATCH + r0) * UNITS + c0 + nf * 8;
            *(unsigned short*)(X + base) =
                __nv_cvt_float2_to_fp8x2(make_float2(p0 * HSCALE, p1 * HSCALE),
                                         __NV_SATFINITE, __NV_E4M3);
            *(unsigned short*)(X + base + 8 * UNITS) =
                __nv_cvt_float2_to_fp8x2(make_float2(p2 * HSCALE, p3 * HSCALE),
                                         __NV_SATFINITE, __NV_E4M3);
        }

        // inter-CTA barrier: one syncthreads, tid0 release-arrives, warps poll
        if (t < SEQ - 1) {
            __syncthreads();
            unsigned* ctr = barRow + t;
            if (tid == 0)
                asm volatile("red.release.gpu.global.add.u32 [%0], %1;"
                             :: "l"(ctr), "r"(1u) : "memory");
            if (lane == 0) {
                unsigned v;
                do {
                    asm volatile("ld.acquire.gpu.global.u32 %0, [%1];"
                                 : "=r"(v) : "l"(ctr) : "memory");
                } while (v < (unsigned)RGRIDX);
            }
            __syncwarp();
        }
    }
}

// ---------------- head ----------------
__global__ void final_kernel(const uint8_t* __restrict__ X,
                             const float* __restrict__ Wo, const float* __restrict__ bo,
                             float* __restrict__ out) {
    int gw   = (blockIdx.x * blockDim.x + threadIdx.x) >> 5;
    int lane = threadIdx.x & 31;
    if (gw >= BATCH) return;
    const uint8_t* h = X + ((size_t)(SEQ - 1) * BATCH + gw) * UNITS;
    float s = 0.0f;
    for (int k = lane; k < UNITS; k += 32) {
        __half_raw hr = __nv_cvt_fp8_to_halfraw(h[k], __NV_E4M3);
        s += __half2float(*(__half*)&hr) * Wo[k];
    }
    #pragma unroll
    for (int o = 16; o; o >>= 1) s += __shfl_xor_sync(0xffffffffu, s, o);
    if (lane == 0) out[gw] = 1.0f / (1.0f + expf(-(s * (1.0f / HSCALE) + bo[0])));
}

// ---------------- host ----------------
extern "C" void kernel_launch(void* const* d_in, const int* in_sizes, int n_in,
                              void* d_out, int out_size) {
    const int*   tokens = (const int*)d_in[0];
    const float* emb    = (const float*)d_in[1];
    const float* W[4]  = {(const float*)d_in[2], (const float*)d_in[5],
                          (const float*)d_in[8], (const float*)d_in[11]};
    const float* U[4]  = {(const float*)d_in[3], (const float*)d_in[6],
                          (const float*)d_in[9], (const float*)d_in[12]};
    const float* bv[4] = {(const float*)d_in[4], (const float*)d_in[7],
                          (const float*)d_in[10], (const float*)d_in[13]};
    const float* Wo = (const float*)d_in[14];
    const float* bo = (const float*)d_in[15];
    float* out = (float*)d_out;

    uint8_t *X0p, *Xp, *W1tp, *Wtp, *Utp;
    __nv_bfloat16* XWp;
    cudaGetSymbolAddress((void**)&X0p,  g_X0);
    cudaGetSymbolAddress((void**)&Xp,   g_X);
    cudaGetSymbolAddress((void**)&XWp,  g_XW);
    cudaGetSymbolAddress((void**)&W1tp, g_W1t);
    cudaGetSymbolAddress((void**)&Wtp,  g_Wt);
    cudaGetSymbolAddress((void**)&Utp,  g_Ut);

    cudaFuncSetAttribute(gemm_fp8, cudaFuncAttributeMaxDynamicSharedMemorySize, XW_SMEM);
    cudaFuncSetAttribute(rnn_fp8,  cudaFuncAttributeMaxDynamicSharedMemorySize, R_SMEM);

    // launch #1, #2: prep (launch #3 = gemm L1, launch #4 = rnn L1 for ncu)
    cvtAll_kernel<<<(512*128 + 7*512*512 + 255) / 256, 256>>>(
        W[0], W[1], W[2], W[3], U[0], U[1], U[2], U[3]);
    embed_zero_kernel<<<(BT * EMBP + 255) / 256, 256>>>(tokens, emb);

    for (int l = 0; l < 4; l++) {
        if (l == 0) {
            gemm_fp8<<<dim3(UNITS / 128, BT / 128), 256, XW_SMEM>>>(
                X0p, EMBP, W1tp, EMBP, bv[0], XWp, 1);
        } else {
            gemm_fp8<<<dim3(UNITS / 128, BT / 128), 256, XW_SMEM>>>(
                Xp, UNITS, Wtp + (size_t)(l - 1) * UNITS * UNITS, UNITS,
                bv[l], XWp, 4);
        }
        rnn_fp8<<<dim3(RGRIDX, RGRIDY), 512, R_SMEM>>>(
            Utp + (size_t)l * UNITS * UNITS, XWp, Xp, l);
    }

    final_kernel<<<BATCH / 8, 256>>>(Xp, Wo, bo, out);
}